// round 16
// baseline (speedup 1.0000x reference)
#include <cuda_runtime.h>
#include <cstdint>

// BoxFilter 9x9 zero-padded window sum. Fixed shape (8,3,1080,1920) fp32, r=4.
//
// v11 = v10's perfectly-balanced warp split + high residency.
//  - 1184 blocks (148 SMs x 8) x 128 thr = 4736 warps, all resident.
//  - Work = 360 column-strips x 1080 rows = 388800 row-units; warp w takes
//    units [w*6075/74, (w+1)*6075/74)  (~82 rows, <=2 segments).
//  - Ring back in SMEM (regs ~50 <= 64 so 8 blocks/SM fit: v10's register
//    ring cost 78 regs -> only 6 blocks -> occ 31% -> latency-bound).
//  - cp.async.cg DEPTH=4 stage ring (136-col rows incl. halos), 3-row slack.

#define RR 4
#define WD 1920
#define HD 1080
#define TILE_W 128               // 32 lanes x float4
#define NTX 15                   // 1920/128
#define WPB 4
#define THREADS 128
#define NBLOCKS 1184             // 148 x 8
#define NWARPS (NBLOCKS * WPB)   // 4736
#define RING 9
#define DEPTH 4
#define CHUNKS 34                // 136 floats = 34 x 16B per stage row

__device__ __forceinline__ float4 f4zero() { return make_float4(0.f, 0.f, 0.f, 0.f); }
__device__ __forceinline__ float4 add4(float4 a, float4 b) {
    return make_float4(a.x + b.x, a.y + b.y, a.z + b.z, a.w + b.w);
}
__device__ __forceinline__ float4 sub4(float4 a, float4 b) {
    return make_float4(a.x - b.x, a.y - b.y, a.z - b.z, a.w - b.w);
}

__device__ __forceinline__ float4 hsum9(float4 p, float4 v, float4 n) {
    const float a0 = p.x, a1 = p.y, a2 = p.z, a3 = p.w;
    const float a4 = v.x, a5 = v.y, a6 = v.z, a7 = v.w;
    const float a8 = n.x, a9 = n.y, a10 = n.z, a11 = n.w;
    const float b0 = a0 + a1, b1 = a2 + a3, b2 = a4 + a5;
    const float b3 = a6 + a7, b4 = a8 + a9, b5 = a10 + a11;
    const float c0 = b0 + b1, c1 = b2 + b3, c2 = b4 + b5;
    float4 h;
    h.x = (c0 + c1) + a8;       // a0..a8
    h.w = (c1 + c2) + a3;       // a3..a11
    h.y = (h.x - a0) + a9;      // a1..a9
    h.z = (h.w - a11) + a2;     // a2..a10
    return h;
}

__global__ __launch_bounds__(THREADS, 8)
void boxfilter9x9_kernel(const float* __restrict__ x, float* __restrict__ out) {
    __shared__ float4 stage_sm[WPB][DEPTH][CHUNKS];   //  8,704 B
    __shared__ float4 ring_sm[WPB][RING][32];         // 18,432 B

    const int warp = threadIdx.x >> 5;
    const int lane = threadIdx.x & 31;
    const uint32_t gwarp = blockIdx.x * WPB + warp;

    float4 (* const mystage)[CHUNKS] = stage_sm[warp];
    float4* const myring = &ring_sm[warp][0][lane];   // slot stride = 32 float4

    // Zero own stage once (covers OOB halo chunks for the first segment).
    for (int i2 = lane; i2 < DEPTH * CHUNKS; i2 += 32)
        (&mystage[0][0])[i2] = f4zero();
    __syncwarp();

    // Even split of 388800 row-units over 4736 warps (388800/4736 = 6075/74).
    uint32_t g  = (uint32_t)((uint64_t)gwarp * 6075u / 74u);
    const uint32_t g1 = (uint32_t)((uint64_t)(gwarp + 1) * 6075u / 74u);

    while (g < g1) {
        const uint32_t s     = g / 1080u;               // column-strip id
        const uint32_t r0    = g - s * 1080u;
        const uint32_t avail = 1080u - r0;
        const uint32_t left  = g1 - g;
        const uint32_t nrows = (avail < left) ? avail : left;

        const uint32_t tx  = s % NTX;
        const uint32_t img = s / NTX;

        const float* __restrict__ base  = x   + (size_t)img * HD * WD;
        float* __restrict__       obase = out + (size_t)img * HD * WD;
        const int col0 = tx * TILE_W;
        const bool skip_c0  = (tx == 0);
        const bool skip_c33 = (tx == NTX - 1);

        // Halo chunks that refill skips must read zero (may hold stale data
        // from a previous segment with different tx).
        if (skip_c0  && lane < DEPTH) mystage[lane][0]  = f4zero();
        if (skip_c33 && lane < DEPTH) mystage[lane][33] = f4zero();
        __syncwarp();

        // Stream input row ir into stage slot; always commits one group.
        auto refill = [&](int ir, int slot) {
            if ((unsigned)ir < (unsigned)HD) {
                const float* rp = base + (size_t)ir * WD + (col0 - 4);  // 16B-aligned
                if (!(skip_c0 && lane == 0)) {
                    unsigned d = (unsigned)__cvta_generic_to_shared(&mystage[slot][lane]);
                    asm volatile("cp.async.cg.shared.global [%0], [%1], 16;"
                                 :: "r"(d), "l"(rp + lane * 4));
                }
                if (lane < 2 && !(skip_c33 && lane == 1)) {
                    unsigned d = (unsigned)__cvta_generic_to_shared(&mystage[slot][32 + lane]);
                    asm volatile("cp.async.cg.shared.global [%0], [%1], 16;"
                                 :: "r"(d), "l"(rp + (32 + lane) * 4));
                }
            } else {
                mystage[slot][lane] = f4zero();
                if (lane < 2) mystage[slot][32 + lane] = f4zero();
            }
            asm volatile("cp.async.commit_group;");
        };

        // ---- prologue A: fill pipeline with first DEPTH input rows ----
#pragma unroll
        for (int k = 0; k < DEPTH; ++k) refill((int)r0 - RR + k, k);

        // ---- prologue B: consume 8 input rows -> smem ring[0..7] ----
        float4 vsum = f4zero();
        int ss = 0;
#pragma unroll
        for (int k = 0; k < 2 * RR; ++k) {
            asm volatile("cp.async.wait_group %0;" :: "n"(DEPTH - 1));
            __syncwarp();
            float4 p = mystage[ss][lane];
            float4 v = mystage[ss][lane + 1];
            float4 n = mystage[ss][lane + 2];
            float4 h = hsum9(p, v, n);
            myring[k * 32] = h;
            vsum = add4(vsum, h);
            refill((int)r0 - RR + k + DEPTH, ss);
            ss = (ss + 1 == DEPTH) ? 0 : ss + 1;
        }

        // ---- main: one output row per consumed input row ----
        int s_old = 0, s_new = 8;
        int irow = (int)r0;
        const int end = (int)(r0 + nrows);
#pragma unroll 2
        while (irow < end) {
            asm volatile("cp.async.wait_group %0;" :: "n"(DEPTH - 1));
            __syncwarp();
            float4 p = mystage[ss][lane];
            float4 v = mystage[ss][lane + 1];
            float4 n = mystage[ss][lane + 2];
            float4 h = hsum9(p, v, n);          // h(irow+4)

            float4 old = myring[s_old * 32];    // h(irow-4)
            myring[s_new * 32] = h;

            vsum = add4(vsum, h);
            __stcs(reinterpret_cast<float4*>(
                       obase + (size_t)irow * WD + col0 + lane * 4), vsum);
            vsum = sub4(vsum, old);

            if (irow + DEPTH < end) refill(irow + RR + DEPTH, ss);
            else asm volatile("cp.async.commit_group;");   // uniform group count

            ss = (ss + 1 == DEPTH) ? 0 : ss + 1;
            s_old = (s_old + 1 == RING) ? 0 : s_old + 1;
            s_new = (s_new + 1 == RING) ? 0 : s_new + 1;
            ++irow;
        }

        // Drain before slots are reused by the next segment.
        asm volatile("cp.async.wait_group 0;");
        __syncwarp();

        g += nrows;
    }
}

extern "C" void kernel_launch(void* const* d_in, const int* in_sizes, int n_in,
                              void* d_out, int out_size) {
    const float* x = (const float*)d_in[0];
    // d_in[1] is r (int32, fixed at 4) — hardcoded.
    float* out = (float*)d_out;
    boxfilter9x9_kernel<<<NBLOCKS, THREADS>>>(x, out);
}